// round 11
// baseline (speedup 1.0000x reference)
#include <cuda_runtime.h>
#include <cstdint>
#include <math.h>

#define CC 1024
#define NROWS (256*1024)

typedef unsigned long long ull;

// Scratch (allocation-free rule: __device__ globals)
__device__ float g_adj[2*CC];
__device__ float g_kcbase[2*CC*64];
__device__ float g_mnext[(size_t)NROWS * 64];
__device__ int   g_mcnt;
__device__ int   g_mlist[65536];

__device__ __forceinline__ float clampf(float v,float lo,float hi){ return fminf(fmaxf(v,lo),hi); }
__device__ __forceinline__ float sigf(float x){ return __fdividef(1.f, 1.f + __expf(-x)); }
__device__ __forceinline__ float tanhfast(float x){
    float t = __expf(-2.f*fabsf(x));
    float r = __fdividef(1.f - t, 1.f + t);
    return copysignf(r, x);
}

// ---- tf32 helpers -----------------------------------------------------------
__device__ __forceinline__ unsigned tf32r(float f){
    unsigned u; asm("cvt.rna.tf32.f32 %0, %1;" : "=r"(u) : "f"(f)); return u;
}
__device__ __forceinline__ float tf32f(float f){ return __uint_as_float(tf32r(f)); }
__device__ __forceinline__ void mma8(float c[4], const unsigned a[4], unsigned b0, unsigned b1){
    asm volatile(
        "mma.sync.aligned.m16n8k8.row.col.f32.tf32.tf32.f32 "
        "{%0,%1,%2,%3},{%4,%5,%6,%7},{%8,%9},{%0,%1,%2,%3};"
        : "+f"(c[0]),"+f"(c[1]),"+f"(c[2]),"+f"(c[3])
        : "r"(a[0]),"r"(a[1]),"r"(a[2]),"r"(a[3]),"r"(b0),"r"(b1));
}
// Fragment-major layout: X[(rowblk*8+ks)*128 + lane*4 + reg]
__device__ __forceinline__ void ldfragX(unsigned a[4], const float* X, int rowblk, int ks, int lane){
    float4 v = *(const float4*)(X + (((rowblk<<3) + ks)<<7) + (lane<<2));
    a[0]=__float_as_uint(v.x); a[1]=__float_as_uint(v.y);
    a[2]=__float_as_uint(v.z); a[3]=__float_as_uint(v.w);
}

// ---------------------------------------------------------------------------
// adj: mask0 has ~5 nonzeros -> compact + gather. Also resets g_mcnt.
// ---------------------------------------------------------------------------
__global__ void adj_kernel(const int* __restrict__ qt,
                           const float* __restrict__ oh,
                           const float* __restrict__ graphs)
{
    __shared__ int   s_idx[CC];
    __shared__ float s_val[CC];
    __shared__ int   s_cnt;
    __shared__ float s_sum;

    int t = threadIdx.x;
    if (t == 0) { s_cnt = 0; s_sum = 0.f; g_mcnt = 0; }
    __syncthreads();

    int q0 = qt[0];
    float m = oh[(size_t)q0 * CC + t];
    if (m != 0.f) {
        int p = atomicAdd(&s_cnt, 1);
        s_idx[p] = t; s_val[p] = m;
        atomicAdd(&s_sum, m);
    }
    __syncthreads();

    float denom = fmaxf(s_sum, 1.f);
    int nnz = s_cnt;
    for (int k = 0; k < 2; k++) {
        float acc = 0.f;
        for (int i = 0; i < nnz; i++)
            acc += s_val[i] * graphs[(size_t)k*CC*CC + (size_t)s_idx[i]*CC + t];
        g_adj[k*CC + t] = clampf(acc / denom, -5.f, 5.f);
    }
}

// ---------------------------------------------------------------------------
// maskscan: compact all masked (b,c) pairs into g_mlist
// ---------------------------------------------------------------------------
__global__ void maskscan_kernel(const int* __restrict__ qt,
                                const float* __restrict__ oh)
{
    int b = blockIdx.x;
    int q = qt[b];
    for (int c = threadIdx.x; c < CC; c += blockDim.x) {
        if (oh[(size_t)q*CC + c] > 0.5f) {
            int p = atomicAdd(&g_mcnt, 1);
            if (p < 65536) g_mlist[p] = (b << 16) | c;
        }
    }
}

// ---------------------------------------------------------------------------
// kcbase[k][c][j] = bn1[k][j] + sum_e clip(kc[c][e],±5) * Wn1[k][192+e][j]
// ---------------------------------------------------------------------------
__global__ void kcbase_kernel(const float* __restrict__ kc,
                              const float* __restrict__ Wn1,
                              const float* __restrict__ bn1)
{
    __shared__ float skc[64];
    int c = blockIdx.x;
    int tid = threadIdx.x;              // 128
    if (tid < 64) skc[tid] = clampf(kc[c*64 + tid], -5.f, 5.f);
    __syncthreads();
    int k = tid >> 6, j = tid & 63;
    float a = bn1[k*64 + j];
    const float* Wp = Wn1 + k*16384 + 12288 + j;
    #pragma unroll 8
    for (int e = 0; e < 64; e++) a = fmaf(skc[e], Wp[e*64], a);
    g_kcbase[((size_t)k*CC + c)*64 + j] = a;
}

// ---------------------------------------------------------------------------
// f1 (tensor tf32, 1024 threads = 32 warps: 4 rg x 8 cg, 32r x 8c per warp)
// ---------------------------------------------------------------------------
__global__ void __launch_bounds__(1024) f1_kernel(
    const float* __restrict__ ht,  const float* __restrict__ nwp,
    const float* __restrict__ Wn1, const float* __restrict__ Wn2,
    const float* __restrict__ bn2)
{
    extern __shared__ float sm[];
    float*  Xs   = sm;                    // 8192 fragment-major tf32(clip(ht))
    float*  H1s  = Xs + 8192;             // 2*8192
    float2* PW1  = (float2*)(H1s + 16384);// 4096 f2
    float2* PW2  = PW1 + 4096;
    float*  sbn2 = (float*)(PW2 + 4096);  // 128
    float*  radj = sbn2 + 128;            // 256

    int tid = threadIdx.x;
    for (int i = tid; i < 4096; i += 1024) {
        int lane = i & 31, nt = (i >> 5) & 7, ks = (i >> 8) & 7, k = i >> 11;
        int t = lane & 3, g = lane >> 2;
        int r0 = ks*8 + t, r1 = r0 + 4, c = nt*8 + g;
        float2 v;
        v.x = __uint_as_float(tf32r(Wn1[k*16384 + (128+r0)*64 + c]));
        v.y = __uint_as_float(tf32r(Wn1[k*16384 + (128+r1)*64 + c]));
        PW1[i] = v;
        v.x = __uint_as_float(tf32r(Wn2[k*4096 + r0*64 + c]));
        v.y = __uint_as_float(tf32r(Wn2[k*4096 + r1*64 + c]));
        PW2[i] = v;
    }
    if (tid < 128) sbn2[tid] = bn2[tid];
    float w = clampf(nwp[0], 0.1f, 0.9f);
    __syncthreads();

    int wid = tid >> 5, lane = tid & 31;
    int rg = wid & 3, cg = wid >> 2;      // rg 0..3, cg 0..7
    int t = lane & 3, g = lane >> 2;
    int rb = rg * 32, cb = cg * 8;
    int q2 = (t >> 1) << 1;
    int l0 = (((g << 2) + ((2*t) & 3)) << 2) + q2;
    int l1 = (((g << 2) + ((2*t + 1)) % 4) << 2) + q2;

    for (int tile = blockIdx.x; tile < NROWS/128; tile += gridDim.x) {
        int row0 = tile << 7;
        int c0 = row0 & 1023;

        // fill Xs = tf32(clip(ht)) fragment-major
        for (int i = tid; i < 2048; i += 1024) {
            int r = i >> 4, q = i & 15;
            float4 v = *(const float4*)(ht + (size_t)(row0+r)*64 + q*4);
            float* p = Xs + ((((r>>4)<<3) + (q>>1))<<7) + ((r&7)<<4) + ((q&1)<<1) + ((r>>3)&1);
            p[0]  = tf32f(clampf(v.x, -5.f, 5.f));
            p[4]  = tf32f(clampf(v.y, -5.f, 5.f));
            p[8]  = tf32f(clampf(v.z, -5.f, 5.f));
            p[12] = tf32f(clampf(v.w, -5.f, 5.f));
        }
        if (tid < 128) {
            int c = (row0 + tid) & 1023;
            radj[tid]       = g_adj[c];
            radj[128 + tid] = g_adj[CC + c];
        }
        __syncthreads();

        // ---- Stage A (both k): acc init from kcbase ----
        float A[2][2][4];   // [k][mt]
        #pragma unroll
        for (int k = 0; k < 2; k++) {
            const float* kcb = g_kcbase + ((size_t)k*CC + c0)*64;
            #pragma unroll
            for (int mt = 0; mt < 2; mt++) {
                int c = cb + 2*t;
                int rA = rb + mt*16 + g;
                float2 v0 = *(const float2*)(kcb + rA*64 + c);
                float2 v1 = *(const float2*)(kcb + (rA+8)*64 + c);
                A[k][mt][0]=v0.x; A[k][mt][1]=v0.y;
                A[k][mt][2]=v1.x; A[k][mt][3]=v1.y;
            }
        }
        #pragma unroll
        for (int ks = 0; ks < 8; ks++) {
            unsigned f0[4], f1v[4];
            ldfragX(f0,  Xs, rg*2,     ks, lane);
            ldfragX(f1v, Xs, rg*2 + 1, ks, lane);
            #pragma unroll
            for (int k = 0; k < 2; k++) {
                int bi = ((k*8 + ks)*8 + cg)*32 + lane;
                float2 bw = PW1[bi];
                unsigned b0 = __float_as_uint(bw.x), b1 = __float_as_uint(bw.y);
                mma8(A[k][0], f0,  b0, b1);
                mma8(A[k][1], f1v, b0, b1);
            }
        }
        // relu + tf32 -> H1s fragment-major
        #pragma unroll
        for (int k = 0; k < 2; k++) {
            float* Hk = H1s + k*8192;
            #pragma unroll
            for (int mt = 0; mt < 2; mt++) {
                float* base = Hk + ((((rg*2+mt)<<3) + cg)<<7);
                base[l0]     = tf32f(fmaxf(A[k][mt][0], 0.f));
                base[l1]     = tf32f(fmaxf(A[k][mt][1], 0.f));
                base[l0 + 1] = tf32f(fmaxf(A[k][mt][2], 0.f));
                base[l1 + 1] = tf32f(fmaxf(A[k][mt][3], 0.f));
            }
        }
        __syncthreads();

        // ---- Stage B (both k) ----
        float B[2][2][4];
        #pragma unroll
        for (int k = 0; k < 2; k++)
            #pragma unroll
            for (int mt = 0; mt < 2; mt++) {
                int c = cb + 2*t;
                float b0 = sbn2[k*64 + c], b1 = sbn2[k*64 + c + 1];
                B[k][mt][0]=b0; B[k][mt][1]=b1; B[k][mt][2]=b0; B[k][mt][3]=b1;
            }
        #pragma unroll
        for (int ks = 0; ks < 8; ks++) {
            unsigned e0[4], e1[4], e2[4], e3[4];
            ldfragX(e0, H1s,        rg*2,     ks, lane);
            ldfragX(e1, H1s,        rg*2 + 1, ks, lane);
            ldfragX(e2, H1s + 8192, rg*2,     ks, lane);
            ldfragX(e3, H1s + 8192, rg*2 + 1, ks, lane);
            int bi0 = ((0*8 + ks)*8 + cg)*32 + lane;
            int bi1 = ((1*8 + ks)*8 + cg)*32 + lane;
            float2 bw = PW2[bi0];
            unsigned b0 = __float_as_uint(bw.x), b1 = __float_as_uint(bw.y);
            mma8(B[0][0], e0, b0, b1); mma8(B[0][1], e1, b0, b1);
            bw = PW2[bi1];
            b0 = __float_as_uint(bw.x); b1 = __float_as_uint(bw.y);
            mma8(B[1][0], e2, b0, b1); mma8(B[1][1], e3, b0, b1);
        }

        // fold nf + write ALL rows (tf32-rounded), row-major global
        #pragma unroll
        for (int mt = 0; mt < 2; mt++) {
            int rA = rb + mt*16 + g;
            float a00 = radj[rA],       a01 = radj[rA + 8];
            float a10 = radj[128 + rA], a11 = radj[128 + rA + 8];
            int c = cb + 2*t;
            float n0 = clampf(a00 * clampf(B[0][mt][0], 0.f, 5.f), -5.f, 5.f);
            float n1 = clampf(a00 * clampf(B[0][mt][1], 0.f, 5.f), -5.f, 5.f);
            float n2 = clampf(a01 * clampf(B[0][mt][2], 0.f, 5.f), -5.f, 5.f);
            float n3 = clampf(a01 * clampf(B[0][mt][3], 0.f, 5.f), -5.f, 5.f);
            float u0 = a10 * clampf(B[1][mt][0], 0.f, 5.f);
            float u1 = a10 * clampf(B[1][mt][1], 0.f, 5.f);
            float u2 = a11 * clampf(B[1][mt][2], 0.f, 5.f);
            float u3 = a11 * clampf(B[1][mt][3], 0.f, 5.f);
            n0 = clampf(w*n0 + (1.f-w)*u0, -5.f, 5.f);
            n1 = clampf(w*n1 + (1.f-w)*u1, -5.f, 5.f);
            n2 = clampf(w*n2 + (1.f-w)*u2, -5.f, 5.f);
            n3 = clampf(w*n3 + (1.f-w)*u3, -5.f, 5.f);
            *(float2*)(&g_mnext[(size_t)(row0+rA)*64 + c])   = make_float2(tf32f(n0), tf32f(n1));
            *(float2*)(&g_mnext[(size_t)(row0+rA+8)*64 + c]) = make_float2(tf32f(n2), tf32f(n3));
        }
        __syncthreads();
    }
}

// ---------------------------------------------------------------------------
// selfmlp fix: one masked (b,c) pair per block, parallel across SMs.
// ---------------------------------------------------------------------------
__global__ void __launch_bounds__(128) selfmlp_kernel(
    const float* __restrict__ ht, const float* __restrict__ kc,
    const float* __restrict__ Ws1, const float* __restrict__ bs1,
    const float* __restrict__ Ws2, const float* __restrict__ bs2)
{
    __shared__ float xr[128];
    __shared__ float hb[64];
    int tid = threadIdx.x;
    int cnt = g_mcnt; if (cnt > 65536) cnt = 65536;

    for (int i = blockIdx.x; i < cnt; i += gridDim.x) {
        int pc = g_mlist[i];
        int b = pc >> 16, c = pc & 0xffff;
        size_t gid = (size_t)b*CC + c;
        xr[tid] = (tid < 64) ? ht[gid*64 + tid] : kc[c*64 + tid - 64];
        __syncthreads();
        if (tid < 64) {
            float a = bs1[tid];
            #pragma unroll 8
            for (int j = 0; j < 128; j++) a = fmaf(xr[j], Ws1[j*64 + tid], a);
            hb[tid] = fmaxf(a, 0.f);
        }
        __syncthreads();
        if (tid < 64) {
            float a = bs2[tid];
            #pragma unroll 8
            for (int j = 0; j < 64; j++) a = fmaf(hb[j], Ws2[j*64 + tid], a);
            g_mnext[gid*64 + tid] = tf32f(clampf(a, 0.f, 10.f));
        }
        __syncthreads();
    }
}

// ---------------------------------------------------------------------------
// f2 (tensor tf32, 1024 threads = 32 warps: 4 rg x 8 cg, 32r x 8c per warp)
// ---------------------------------------------------------------------------
__global__ void __launch_bounds__(1024) f2_kernel(
    const float* __restrict__ ht,  const float* __restrict__ ea_w,
    const float* __restrict__ We,  const float* __restrict__ be,
    const float* __restrict__ Wa,  const float* __restrict__ ba,
    const float* __restrict__ Wih, const float* __restrict__ bih,
    const float* __restrict__ Whh, const float* __restrict__ bhh,
    const float* __restrict__ Wp,  const float* __restrict__ bp,
    float* __restrict__ out)
{
    extern __shared__ float sm[];
    float*  Xs   = sm;                       // 8192 frag-major (m, then res)
    float*  Hs   = Xs + 8192;                // 8192 frag-major (ht)
    float2* PWe  = (float2*)(Hs + 8192);     // 2048 f2
    float2* PWa  = PWe + 2048;
    float2* PWih = PWa + 2048;               // 6144 f2
    float2* PWhh = PWih + 6144;
    float*  sbe  = (float*)(PWhh + 6144);
    float*  sba  = sbe + 64;
    float*  sbrz = sba + 64;
    float*  sbI  = sbrz + 128;
    float*  sbH  = sbI + 64;
    float*  sWp  = sbH + 64;
    float*  sred = sWp + 64;                 // 1024

    int tid = threadIdx.x;

    for (int i = tid; i < 2048; i += 1024) {
        int lane = i & 31, nt = (i >> 5) & 7, ks = i >> 8;
        int t = lane & 3, g = lane >> 2;
        int r0 = ks*8 + t, r1 = r0 + 4, c = nt*8 + g;
        float2 v;
        v.x = __uint_as_float(tf32r(We[r0*64 + c]));
        v.y = __uint_as_float(tf32r(We[r1*64 + c]));
        PWe[i] = v;
        v.x = __uint_as_float(tf32r(Wa[r0*64 + c]));
        v.y = __uint_as_float(tf32r(Wa[r1*64 + c]));
        PWa[i] = v;
    }
    for (int i = tid; i < 6144; i += 1024) {
        int lane = i & 31; int rest = i >> 5; int nt = rest % 24, ks = rest / 24;
        int t = lane & 3, g = lane >> 2;
        int r0 = ks*8 + t, r1 = r0 + 4, c = nt*8 + g;
        float2 v;
        v.x = __uint_as_float(tf32r(Wih[r0*192 + c]));
        v.y = __uint_as_float(tf32r(Wih[r1*192 + c]));
        PWih[i] = v;
        v.x = __uint_as_float(tf32r(Whh[r0*192 + c]));
        v.y = __uint_as_float(tf32r(Whh[r1*192 + c]));
        PWhh[i] = v;
    }
    if (tid < 64) {
        sbe[tid] = be[tid]; sba[tid] = ba[tid]; sWp[tid] = Wp[tid];
        sbI[tid] = bih[128 + tid]; sbH[tid] = bhh[128 + tid];
    }
    if (tid < 128) sbrz[tid] = bih[tid] + bhh[tid];
    float bpv = bp[0];
    __syncthreads();

    int wid = tid >> 5, lane = tid & 31;
    int rg = wid & 3, cg = wid >> 2;     // rg 0..3, cg 0..7
    int t = lane & 3, g = lane >> 2;
    int rb = rg * 32, cb = cg * 8;
    int q2 = (t >> 1) << 1;
    int l0 = (((g << 2) + ((2*t) & 3)) << 2) + q2;
    int l1 = (((g << 2) + ((2*t + 1)) % 4) << 2) + q2;

    for (int tile = blockIdx.x; tile < NROWS/128; tile += gridDim.x) {
        int row0 = tile << 7;

        for (int i = tid; i < 2048; i += 1024) {
            int r = i >> 4, q = i & 15;
            float4 m4 = *(const float4*)(g_mnext + (size_t)(row0+r)*64 + q*4);  // already tf32
            float4 h4 = *(const float4*)(ht      + (size_t)(row0+r)*64 + q*4);
            int off = ((((r>>4)<<3) + (q>>1))<<7) + ((r&7)<<4) + ((q&1)<<1) + ((r>>3)&1);
            float* px = Xs + off;
            px[0] = m4.x; px[4] = m4.y; px[8] = m4.z; px[12] = m4.w;
            float* ph = Hs + off;
            ph[0] = tf32f(h4.x); ph[4] = tf32f(h4.y); ph[8] = tf32f(h4.z); ph[12] = tf32f(h4.w);
        }
        __syncthreads();

        // ---- Phase A ----
        float S[2][4], T[2][4];
        {
            int c = cb + 2*t;
            float be0 = sbe[c], be1 = sbe[c+1];
            float ba0 = sba[c], ba1 = sba[c+1];
            #pragma unroll
            for (int mt = 0; mt < 2; mt++) {
                S[mt][0]=be0; S[mt][1]=be1; S[mt][2]=be0; S[mt][3]=be1;
                T[mt][0]=ba0; T[mt][1]=ba1; T[mt][2]=ba0; T[mt][3]=ba1;
            }
        }
        #pragma unroll
        for (int ks = 0; ks < 8; ks++) {
            unsigned f0[4], f1[4];
            ldfragX(f0, Xs, rg*2,     ks, lane);
            ldfragX(f1, Xs, rg*2 + 1, ks, lane);
            int bi = (ks*8 + cg)*32 + lane;
            float2 bw = PWe[bi];
            unsigned b0 = __float_as_uint(bw.x), b1 = __float_as_uint(bw.y);
            mma8(S[0], f0, b0, b1); mma8(S[1], f1, b0, b1);
            bw = PWa[bi];
            b0 = __float_as_uint(bw.x); b1 = __float_as_uint(bw.y);
            mma8(T[0], f0, b0, b1); mma8(T[1], f1, b0, b1);
        }

        float resv[2][4];
        float ga[4];
        #pragma unroll
        for (int q = 0; q < 4; q++)
            ga[q] = ea_w[(row0 + rb + (q>>1)*16 + (q&1)*8 + g) & 1023];
        #pragma unroll
        for (int mt = 0; mt < 2; mt++) {
            const float* base = Xs + ((((rg*2+mt)<<3) + cg)<<7);
            float m00 = base[l0], m01 = base[l1];
            float m10 = base[l0 + 1], m11 = base[l1 + 1];
            float g0 = ga[2*mt], g1 = ga[2*mt+1];
            resv[mt][0] = m00 - g0*sigf(S[mt][0])*m00 + g0*tanhfast(T[mt][0]);
            resv[mt][1] = m01 - g0*sigf(S[mt][1])*m01 + g0*tanhfast(T[mt][1]);
            resv[mt][2] = m10 - g1*sigf(S[mt][2])*m10 + g1*tanhfast(T[mt][2]);
            resv[mt][3] = m11 - g1*sigf(S[mt][3])*m11 + g1*tanhfast(T[mt][3]);
        }
        __syncthreads();
        #pragma unroll
        for (int mt = 0; mt < 2; mt++) {
            float* base = Xs + ((((rg*2+mt)<<3) + cg)<<7);
            base[l0]     = tf32f(resv[mt][0]);
            base[l1]     = tf32f(resv[mt][1]);
            base[l0 + 1] = tf32f(resv[mt][2]);
            base[l1 + 1] = tf32f(resv[mt][3]);
        }
        __syncthreads();

        // ---- Phase BC ----
        float R[2][4], Z[2][4], I_[2][4], Hh[2][4];
        {
            int c = cb + 2*t;
            float r0v = sbrz[c], r1v = sbrz[c+1];
            float z0v = sbrz[64+c], z1v = sbrz[64+c+1];
            float i0v = sbI[c], i1v = sbI[c+1];
            float h0v = sbH[c], h1v = sbH[c+1];
            #pragma unroll
            for (int mt = 0; mt < 2; mt++) {
                R[mt][0]=r0v; R[mt][1]=r1v; R[mt][2]=r0v; R[mt][3]=r1v;
                Z[mt][0]=z0v; Z[mt][1]=z1v; Z[mt][2]=z0v; Z[mt][3]=z1v;
                I_[mt][0]=i0v; I_[mt][1]=i1v; I_[mt][2]=i0v; I_[mt][3]=i1v;
                Hh[mt][0]=h0v; Hh[mt][1]=h1v; Hh[mt][2]=h0v; Hh[mt][3]=h1v;
            }
        }
        #pragma unroll
        for (int ks = 0; ks < 8; ks++) {
            unsigned f0[4], f1[4];
            ldfragX(f0, Xs, rg*2,     ks, lane);
            ldfragX(f1, Xs, rg*2 + 1, ks, lane);
            int bi = (ks*24 + cg)*32 + lane;
            float2 bw = PWih[bi];
            unsigned b0 = __float_as_uint(bw.x), b1 = __float_as_uint(bw.y);
            mma8(R[0], f0, b0, b1); mma8(R[1], f1, b0, b1);
            bw = PWih[bi + 256];
            b0 = __float_as_uint(bw.x); b1 = __float_as_uint(bw.y);
            mma8(Z[0], f0, b0, b1); mma8(Z[1], f1, b0, b1);
            bw = PWih[bi + 512];
            b0 = __float_as_uint(bw.x); b1 = __float_as_uint(bw.y);
            mma8(I_[0], f0, b0, b1); mma8(I_[1], f1, b0, b1);

            ldfragX(f0, Hs, rg*2,     ks, lane);
            ldfragX(f1, Hs, rg*2 + 1, ks, lane);
            bw = PWhh[bi];
            b0 = __float_as_uint(bw.x); b1 = __float_as_uint(bw.y);
            mma8(R[0], f0, b0, b1); mma8(R[1], f1, b0, b1);
            bw = PWhh[bi + 256];
            b0 = __float_as_uint(bw.x); b1 = __float_as_uint(bw.y);
            mma8(Z[0], f0, b0, b1); mma8(Z[1], f1, b0, b1);
            bw = PWhh[bi + 512];
            b0 = __float_as_uint(bw.x); b1 = __float_as_uint(bw.y);
            mma8(Hh[0], f0, b0, b1); mma8(Hh[1], f1, b0, b1);
        }

        float py[4] = {0.f, 0.f, 0.f, 0.f};
        #pragma unroll
        for (int mt = 0; mt < 2; mt++) {
            int c = cb + 2*t;
            const float* hbase = Hs + ((((rg*2+mt)<<3) + cg)<<7);
            float h00 = hbase[l0], h01 = hbase[l1];
            float h10 = hbase[l0 + 1], h11 = hbase[l1 + 1];
            float wc0 = sWp[c], wc1 = sWp[c+1];
            {
                float rr = sigf(R[mt][0]), zz = sigf(Z[mt][0]);
                float nn = tanhfast(I_[mt][0] + rr*Hh[mt][0]);
                py[2*mt] = fmaf((1.f-zz)*nn + zz*h00, wc0, py[2*mt]);
            }
            {
                float rr = sigf(R[mt][1]), zz = sigf(Z[mt][1]);
                float nn = tanhfast(I_[mt][1] + rr*Hh[mt][1]);
                py[2*mt] = fmaf((1.f-zz)*nn + zz*h01, wc1, py[2*mt]);
            }
            {
                float rr = sigf(R[mt][2]), zz = sigf(Z[mt][2]);
                float nn = tanhfast(I_[mt][2] + rr*Hh[mt][2]);
                py[2*mt+1] = fmaf((1.f-zz)*nn + zz*h10, wc0, py[2*mt+1]);
            }
            {
                float rr = sigf(R[mt][3]), zz = sigf(Z[mt][3]);
                float nn = tanhfast(I_[mt][3] + rr*Hh[mt][3]);
                py[2*mt+1] = fmaf((1.f-zz)*nn + zz*h11, wc1, py[2*mt+1]);
            }
        }
        #pragma unroll
        for (int q = 0; q < 4; q++) {
            py[q] += __shfl_xor_sync(0xffffffffu, py[q], 1, 4);
            py[q] += __shfl_xor_sync(0xffffffffu, py[q], 2, 4);
        }
        if (t == 0) {
            sred[cg*128 + rb + g]      = py[0];
            sred[cg*128 + rb + 8 + g]  = py[1];
            sred[cg*128 + rb + 16 + g] = py[2];
            sred[cg*128 + rb + 24 + g] = py[3];
        }
        __syncthreads();
        if (tid < 128) {
            float acc = bpv;
            #pragma unroll
            for (int q = 0; q < 8; q++) acc += sred[q*128 + tid];
            out[row0 + tid] = sigf(acc);
        }
        __syncthreads();
    }
}

// ---------------------------------------------------------------------------
extern "C" void kernel_launch(void* const* d_in, const int* in_sizes, int n_in,
                              void* d_out, int out_size)
{
    const int*   qt  = (const int*)  d_in[1];
    const float* ht  = (const float*)d_in[2];
    const float* oh  = (const float*)d_in[3];
    const float* kc  = (const float*)d_in[4];
    const float* gr  = (const float*)d_in[5];
    const float* nw  = (const float*)d_in[6];
    const float* Ws1 = (const float*)d_in[7];
    const float* bs1 = (const float*)d_in[8];
    const float* Ws2 = (const float*)d_in[9];
    const float* bs2 = (const float*)d_in[10];
    const float* Wn1 = (const float*)d_in[11];
    const float* bn1 = (const float*)d_in[12];
    const float* Wn2 = (const float*)d_in[13];
    const float* bn2 = (const float*)d_in[14];
    const float* ea  = (const float*)d_in[15];
    const float* We  = (const float*)d_in[16];
    const float* be  = (const float*)d_in[17];
    const float* Wa  = (const float*)d_in[18];
    const float* ba  = (const float*)d_in[19];
    const float* Wih = (const float*)d_in[20];
    const float* bih = (const float*)d_in[21];
    const float* Whh = (const float*)d_in[22];
    const float* bhh = (const float*)d_in[23];
    const float* Wp  = (const float*)d_in[24];
    const float* bp  = (const float*)d_in[25];
    float* out = (float*)d_out;

    int smc = 148;
    if (cudaDeviceGetAttribute(&smc, cudaDevAttrMultiProcessorCount, 0) != cudaSuccess || smc <= 0)
        smc = 148;

    size_t smem1 = (size_t)(8192 + 16384 + 8192 + 8192 + 128 + 256) * 4;   // 165,376 B
    size_t smem2 = (size_t)(8192 + 8192 + 4096 + 4096 + 12288 + 12288 + 64+64+128+64+64+64+1024) * 4;  // 202,496 B
    cudaFuncSetAttribute(f1_kernel, cudaFuncAttributeMaxDynamicSharedMemorySize, (int)smem1);
    cudaFuncSetAttribute(f2_kernel, cudaFuncAttributeMaxDynamicSharedMemorySize, (int)smem2);

    adj_kernel<<<1, 1024>>>(qt, oh, gr);
    maskscan_kernel<<<256, 256>>>(qt, oh);
    kcbase_kernel<<<1024, 128>>>(kc, Wn1, bn1);
    f1_kernel<<<smc, 1024, smem1>>>(ht, nw, Wn1, Wn2, bn2);
    selfmlp_kernel<<<2048, 128>>>(ht, kc, Ws1, bs1, Ws2, bs2);
    f2_kernel<<<smc, 1024, smem2>>>(ht, ea, We, be, Wa, ba, Wih, bih, Whh, bhh, Wp, bp, out);
}

// round 12
// speedup vs baseline: 1.0670x; 1.0670x over previous
#include <cuda_runtime.h>
#include <cstdint>
#include <math.h>

#define CC 1024
#define NROWS (256*1024)

typedef unsigned long long ull;

// Scratch (allocation-free rule: __device__ globals)
__device__ float g_adj[2*CC];
__device__ float g_kcbase[2*CC*64];
__device__ float g_mnext[(size_t)NROWS * 64];
__device__ int   g_mcnt;
__device__ int   g_mlist[65536];

__device__ __forceinline__ float clampf(float v,float lo,float hi){ return fminf(fmaxf(v,lo),hi); }
__device__ __forceinline__ float sigf(float x){ return __fdividef(1.f, 1.f + __expf(-x)); }
__device__ __forceinline__ float tanhfast(float x){
    float t = __expf(-2.f*fabsf(x));
    float r = __fdividef(1.f - t, 1.f + t);
    return copysignf(r, x);
}

// ---- tf32 helpers -----------------------------------------------------------
__device__ __forceinline__ unsigned tf32r(float f){
    unsigned u; asm("cvt.rna.tf32.f32 %0, %1;" : "=r"(u) : "f"(f)); return u;
}
__device__ __forceinline__ float tf32f(float f){ return __uint_as_float(tf32r(f)); }
__device__ __forceinline__ void mma8(float c[4], const unsigned a[4], unsigned b0, unsigned b1){
    asm volatile(
        "mma.sync.aligned.m16n8k8.row.col.f32.tf32.tf32.f32 "
        "{%0,%1,%2,%3},{%4,%5,%6,%7},{%8,%9},{%0,%1,%2,%3};"
        : "+f"(c[0]),"+f"(c[1]),"+f"(c[2]),"+f"(c[3])
        : "r"(a[0]),"r"(a[1]),"r"(a[2]),"r"(a[3]),"r"(b0),"r"(b1));
}
// Fragment-major layout: X[(rowblk*8+ks)*128 + lane*4 + reg]
__device__ __forceinline__ void ldfragX(unsigned a[4], const float* X, int rowblk, int ks, int lane){
    float4 v = *(const float4*)(X + (((rowblk<<3) + ks)<<7) + (lane<<2));
    a[0]=__float_as_uint(v.x); a[1]=__float_as_uint(v.y);
    a[2]=__float_as_uint(v.z); a[3]=__float_as_uint(v.w);
}

// ---------------------------------------------------------------------------
// adj: mask0 has ~5 nonzeros -> compact + gather. Also resets g_mcnt.
// ---------------------------------------------------------------------------
__global__ void adj_kernel(const int* __restrict__ qt,
                           const float* __restrict__ oh,
                           const float* __restrict__ graphs)
{
    __shared__ int   s_idx[CC];
    __shared__ float s_val[CC];
    __shared__ int   s_cnt;
    __shared__ float s_sum;

    int t = threadIdx.x;
    if (t == 0) { s_cnt = 0; s_sum = 0.f; g_mcnt = 0; }
    __syncthreads();

    int q0 = qt[0];
    float m = oh[(size_t)q0 * CC + t];
    if (m != 0.f) {
        int p = atomicAdd(&s_cnt, 1);
        s_idx[p] = t; s_val[p] = m;
        atomicAdd(&s_sum, m);
    }
    __syncthreads();

    float denom = fmaxf(s_sum, 1.f);
    int nnz = s_cnt;
    for (int k = 0; k < 2; k++) {
        float acc = 0.f;
        for (int i = 0; i < nnz; i++)
            acc += s_val[i] * graphs[(size_t)k*CC*CC + (size_t)s_idx[i]*CC + t];
        g_adj[k*CC + t] = clampf(acc / denom, -5.f, 5.f);
    }
}

// ---------------------------------------------------------------------------
// maskscan: compact all masked (b,c) pairs into g_mlist
// ---------------------------------------------------------------------------
__global__ void maskscan_kernel(const int* __restrict__ qt,
                                const float* __restrict__ oh)
{
    int b = blockIdx.x;
    int q = qt[b];
    for (int c = threadIdx.x; c < CC; c += blockDim.x) {
        if (oh[(size_t)q*CC + c] > 0.5f) {
            int p = atomicAdd(&g_mcnt, 1);
            if (p < 65536) g_mlist[p] = (b << 16) | c;
        }
    }
}

// ---------------------------------------------------------------------------
// kcbase[k][c][j] = bn1[k][j] + sum_e clip(kc[c][e],±5) * Wn1[k][192+e][j]
// ---------------------------------------------------------------------------
__global__ void kcbase_kernel(const float* __restrict__ kc,
                              const float* __restrict__ Wn1,
                              const float* __restrict__ bn1)
{
    __shared__ float skc[64];
    int c = blockIdx.x;
    int tid = threadIdx.x;              // 128
    if (tid < 64) skc[tid] = clampf(kc[c*64 + tid], -5.f, 5.f);
    __syncthreads();
    int k = tid >> 6, j = tid & 63;
    float a = bn1[k*64 + j];
    const float* Wp = Wn1 + k*16384 + 12288 + j;
    #pragma unroll 8
    for (int e = 0; e < 64; e++) a = fmaf(skc[e], Wp[e*64], a);
    g_kcbase[((size_t)k*CC + c)*64 + j] = a;
}

// ---------------------------------------------------------------------------
// f1 (tensor tf32, fragment-major, 512 threads, register-pipelined fills)
// ---------------------------------------------------------------------------
__global__ void __launch_bounds__(512) f1_kernel(
    const float* __restrict__ ht,  const float* __restrict__ nwp,
    const float* __restrict__ Wn1, const float* __restrict__ Wn2,
    const float* __restrict__ bn2)
{
    extern __shared__ float sm[];
    float*  Xs   = sm;                    // 8192 fragment-major tf32(clip(ht))
    float*  H1s  = Xs + 8192;             // 2*8192
    float2* PW1  = (float2*)(H1s + 16384);// 4096 f2
    float2* PW2  = PW1 + 4096;
    float*  sbn2 = (float*)(PW2 + 4096);  // 128
    float*  radj = sbn2 + 128;            // 256

    int tid = threadIdx.x;
    for (int i = tid; i < 4096; i += 512) {
        int lane = i & 31, nt = (i >> 5) & 7, ks = (i >> 8) & 7, k = i >> 11;
        int t = lane & 3, g = lane >> 2;
        int r0 = ks*8 + t, r1 = r0 + 4, c = nt*8 + g;
        float2 v;
        v.x = __uint_as_float(tf32r(Wn1[k*16384 + (128+r0)*64 + c]));
        v.y = __uint_as_float(tf32r(Wn1[k*16384 + (128+r1)*64 + c]));
        PW1[i] = v;
        v.x = __uint_as_float(tf32r(Wn2[k*4096 + r0*64 + c]));
        v.y = __uint_as_float(tf32r(Wn2[k*4096 + r1*64 + c]));
        PW2[i] = v;
    }
    if (tid < 128) sbn2[tid] = bn2[tid];
    float w = clampf(nwp[0], 0.1f, 0.9f);
    __syncthreads();

    int wid = tid >> 5, lane = tid & 31;
    int rg = wid & 3, cg = wid >> 2;
    int t = lane & 3, g = lane >> 2;
    int rb = rg * 32, cb = cg * 16;
    int q2 = (t >> 1) << 1;
    int l0 = (((g << 2) + ((2*t) & 3)) << 2) + q2;
    int l1 = (((g << 2) + ((2*t + 1)) % 4) << 2) + q2;

    const int NT = NROWS/128;
    // fill indices for this thread (4 chunks)
    int fr[4], fq[4];
    #pragma unroll
    for (int ii = 0; ii < 4; ii++) { int i = tid + ii*512; fr[ii] = i >> 4; fq[ii] = i & 15; }

    float4 pf[4];
    int tile = blockIdx.x;
    if (tile < NT) {
        int row0 = tile << 7;
        #pragma unroll
        for (int ii = 0; ii < 4; ii++)
            pf[ii] = *(const float4*)(ht + (size_t)(row0 + fr[ii])*64 + fq[ii]*4);
    }

    for (; tile < NT; tile += gridDim.x) {
        int row0 = tile << 7;
        int c0 = row0 & 1023;

        // store prefetched tile into Xs (fragment-major)
        #pragma unroll
        for (int ii = 0; ii < 4; ii++) {
            int r = fr[ii], q = fq[ii];
            float4 v = pf[ii];
            float* p = Xs + ((((r>>4)<<3) + (q>>1))<<7) + ((r&7)<<4) + ((q&1)<<1) + ((r>>3)&1);
            p[0]  = tf32f(clampf(v.x, -5.f, 5.f));
            p[4]  = tf32f(clampf(v.y, -5.f, 5.f));
            p[8]  = tf32f(clampf(v.z, -5.f, 5.f));
            p[12] = tf32f(clampf(v.w, -5.f, 5.f));
        }
        if (tid < 128) {
            int c = (row0 + tid) & 1023;
            radj[tid]       = g_adj[c];
            radj[128 + tid] = g_adj[CC + c];
        }
        __syncthreads();

        // prefetch next tile (overlaps with compute below)
        int nxt = tile + gridDim.x;
        if (nxt < NT) {
            int nrow0 = nxt << 7;
            #pragma unroll
            for (int ii = 0; ii < 4; ii++)
                pf[ii] = *(const float4*)(ht + (size_t)(nrow0 + fr[ii])*64 + fq[ii]*4);
        }

        // ---- Stage A (both k): acc init from kcbase ----
        float A[2][2][2][4];
        #pragma unroll
        for (int k = 0; k < 2; k++) {
            const float* kcb = g_kcbase + ((size_t)k*CC + c0)*64;
            #pragma unroll
            for (int mt = 0; mt < 2; mt++)
                #pragma unroll
                for (int nt = 0; nt < 2; nt++) {
                    int c = cb + nt*8 + 2*t;
                    int rA = rb + mt*16 + g;
                    float2 v0 = *(const float2*)(kcb + rA*64 + c);
                    float2 v1 = *(const float2*)(kcb + (rA+8)*64 + c);
                    A[k][mt][nt][0]=v0.x; A[k][mt][nt][1]=v0.y;
                    A[k][mt][nt][2]=v1.x; A[k][mt][nt][3]=v1.y;
                }
        }
        #pragma unroll
        for (int ks = 0; ks < 8; ks++) {
            unsigned f0[4], f1v[4];
            ldfragX(f0,  Xs, rg*2,     ks, lane);
            ldfragX(f1v, Xs, rg*2 + 1, ks, lane);
            #pragma unroll
            for (int k = 0; k < 2; k++)
                #pragma unroll
                for (int nt = 0; nt < 2; nt++) {
                    int bi = ((k*8 + ks)*8 + cg*2 + nt)*32 + lane;
                    float2 bw = PW1[bi];
                    unsigned b0 = __float_as_uint(bw.x), b1 = __float_as_uint(bw.y);
                    mma8(A[k][0][nt], f0,  b0, b1);
                    mma8(A[k][1][nt], f1v, b0, b1);
                }
        }
        // relu + tf32 -> H1s fragment-major
        #pragma unroll
        for (int k = 0; k < 2; k++) {
            float* Hk = H1s + k*8192;
            #pragma unroll
            for (int mt = 0; mt < 2; mt++)
                #pragma unroll
                for (int nt = 0; nt < 2; nt++) {
                    float* base = Hk + ((((rg*2+mt)<<3) + (cg*2+nt))<<7);
                    base[l0]     = tf32f(fmaxf(A[k][mt][nt][0], 0.f));
                    base[l1]     = tf32f(fmaxf(A[k][mt][nt][1], 0.f));
                    base[l0 + 1] = tf32f(fmaxf(A[k][mt][nt][2], 0.f));
                    base[l1 + 1] = tf32f(fmaxf(A[k][mt][nt][3], 0.f));
                }
        }
        __syncthreads();

        // ---- Stage B (both k) ----
        float B[2][2][2][4];
        #pragma unroll
        for (int k = 0; k < 2; k++)
            #pragma unroll
            for (int mt = 0; mt < 2; mt++)
                #pragma unroll
                for (int nt = 0; nt < 2; nt++) {
                    int c = cb + nt*8 + 2*t;
                    float b0 = sbn2[k*64 + c], b1 = sbn2[k*64 + c + 1];
                    B[k][mt][nt][0]=b0; B[k][mt][nt][1]=b1; B[k][mt][nt][2]=b0; B[k][mt][nt][3]=b1;
                }
        #pragma unroll
        for (int ks = 0; ks < 8; ks++) {
            unsigned e0[4], e1[4], e2[4], e3[4];
            ldfragX(e0, H1s,        rg*2,     ks, lane);
            ldfragX(e1, H1s,        rg*2 + 1, ks, lane);
            ldfragX(e2, H1s + 8192, rg*2,     ks, lane);
            ldfragX(e3, H1s + 8192, rg*2 + 1, ks, lane);
            #pragma unroll
            for (int nt = 0; nt < 2; nt++) {
                int bi0 = ((0*8 + ks)*8 + cg*2 + nt)*32 + lane;
                int bi1 = ((1*8 + ks)*8 + cg*2 + nt)*32 + lane;
                float2 bw = PW2[bi0];
                unsigned b0 = __float_as_uint(bw.x), b1 = __float_as_uint(bw.y);
                mma8(B[0][0][nt], e0, b0, b1); mma8(B[0][1][nt], e1, b0, b1);
                bw = PW2[bi1];
                b0 = __float_as_uint(bw.x); b1 = __float_as_uint(bw.y);
                mma8(B[1][0][nt], e2, b0, b1); mma8(B[1][1][nt], e3, b0, b1);
            }
        }

        // fold nf + write ALL rows (tf32-rounded), row-major global
        #pragma unroll
        for (int mt = 0; mt < 2; mt++) {
            int rA = rb + mt*16 + g;
            float a00 = radj[rA],       a01 = radj[rA + 8];
            float a10 = radj[128 + rA], a11 = radj[128 + rA + 8];
            #pragma unroll
            for (int nt = 0; nt < 2; nt++) {
                int c = cb + nt*8 + 2*t;
                float n0 = clampf(a00 * clampf(B[0][mt][nt][0], 0.f, 5.f), -5.f, 5.f);
                float n1 = clampf(a00 * clampf(B[0][mt][nt][1], 0.f, 5.f), -5.f, 5.f);
                float n2 = clampf(a01 * clampf(B[0][mt][nt][2], 0.f, 5.f), -5.f, 5.f);
                float n3 = clampf(a01 * clampf(B[0][mt][nt][3], 0.f, 5.f), -5.f, 5.f);
                float u0 = a10 * clampf(B[1][mt][nt][0], 0.f, 5.f);
                float u1 = a10 * clampf(B[1][mt][nt][1], 0.f, 5.f);
                float u2 = a11 * clampf(B[1][mt][nt][2], 0.f, 5.f);
                float u3 = a11 * clampf(B[1][mt][nt][3], 0.f, 5.f);
                n0 = clampf(w*n0 + (1.f-w)*u0, -5.f, 5.f);
                n1 = clampf(w*n1 + (1.f-w)*u1, -5.f, 5.f);
                n2 = clampf(w*n2 + (1.f-w)*u2, -5.f, 5.f);
                n3 = clampf(w*n3 + (1.f-w)*u3, -5.f, 5.f);
                *(float2*)(&g_mnext[(size_t)(row0+rA)*64 + c])   = make_float2(tf32f(n0), tf32f(n1));
                *(float2*)(&g_mnext[(size_t)(row0+rA+8)*64 + c]) = make_float2(tf32f(n2), tf32f(n3));
            }
        }
        __syncthreads();
    }
}

// ---------------------------------------------------------------------------
// selfmlp fix: one masked (b,c) pair per block, parallel across SMs.
// ---------------------------------------------------------------------------
__global__ void __launch_bounds__(128) selfmlp_kernel(
    const float* __restrict__ ht, const float* __restrict__ kc,
    const float* __restrict__ Ws1, const float* __restrict__ bs1,
    const float* __restrict__ Ws2, const float* __restrict__ bs2)
{
    __shared__ float xr[128];
    __shared__ float hb[64];
    int tid = threadIdx.x;
    int cnt = g_mcnt; if (cnt > 65536) cnt = 65536;

    for (int i = blockIdx.x; i < cnt; i += gridDim.x) {
        int pc = g_mlist[i];
        int b = pc >> 16, c = pc & 0xffff;
        size_t gid = (size_t)b*CC + c;
        xr[tid] = (tid < 64) ? ht[gid*64 + tid] : kc[c*64 + tid - 64];
        __syncthreads();
        if (tid < 64) {
            float a = bs1[tid];
            #pragma unroll 8
            for (int j = 0; j < 128; j++) a = fmaf(xr[j], Ws1[j*64 + tid], a);
            hb[tid] = fmaxf(a, 0.f);
        }
        __syncthreads();
        if (tid < 64) {
            float a = bs2[tid];
            #pragma unroll 8
            for (int j = 0; j < 64; j++) a = fmaf(hb[j], Ws2[j*64 + tid], a);
            g_mnext[gid*64 + tid] = tf32f(clampf(a, 0.f, 10.f));
        }
        __syncthreads();
    }
}

// ---------------------------------------------------------------------------
// f2 (tensor tf32, fragment-major, 512 threads, register-pipelined fills)
// ---------------------------------------------------------------------------
__global__ void __launch_bounds__(512) f2_kernel(
    const float* __restrict__ ht,  const float* __restrict__ ea_w,
    const float* __restrict__ We,  const float* __restrict__ be,
    const float* __restrict__ Wa,  const float* __restrict__ ba,
    const float* __restrict__ Wih, const float* __restrict__ bih,
    const float* __restrict__ Whh, const float* __restrict__ bhh,
    const float* __restrict__ Wp,  const float* __restrict__ bp,
    float* __restrict__ out)
{
    extern __shared__ float sm[];
    float*  Xs   = sm;                       // 8192 (m tf32, then res tf32) frag-major
    float*  Hs   = Xs + 8192;                // 8192 (ht tf32) frag-major
    float2* PWe  = (float2*)(Hs + 8192);     // 2048 f2
    float2* PWa  = PWe + 2048;
    float2* PWih = PWa + 2048;               // 6144 f2
    float2* PWhh = PWih + 6144;
    float*  sbe  = (float*)(PWhh + 6144);
    float*  sba  = sbe + 64;
    float*  sbrz = sba + 64;
    float*  sbI  = sbrz + 128;
    float*  sbH  = sbI + 64;
    float*  sWp  = sbH + 64;
    float*  sred = sWp + 64;                 // 512

    int tid = threadIdx.x;

    for (int i = tid; i < 2048; i += 512) {
        int lane = i & 31, nt = (i >> 5) & 7, ks = i >> 8;
        int t = lane & 3, g = lane >> 2;
        int r0 = ks*8 + t, r1 = r0 + 4, c = nt*8 + g;
        float2 v;
        v.x = __uint_as_float(tf32r(We[r0*64 + c]));
        v.y = __uint_as_float(tf32r(We[r1*64 + c]));
        PWe[i] = v;
        v.x = __uint_as_float(tf32r(Wa[r0*64 + c]));
        v.y = __uint_as_float(tf32r(Wa[r1*64 + c]));
        PWa[i] = v;
    }
    for (int i = tid; i < 6144; i += 512) {
        int lane = i & 31; int rest = i >> 5; int nt = rest % 24, ks = rest / 24;
        int t = lane & 3, g = lane >> 2;
        int r0 = ks*8 + t, r1 = r0 + 4, c = nt*8 + g;
        float2 v;
        v.x = __uint_as_float(tf32r(Wih[r0*192 + c]));
        v.y = __uint_as_float(tf32r(Wih[r1*192 + c]));
        PWih[i] = v;
        v.x = __uint_as_float(tf32r(Whh[r0*192 + c]));
        v.y = __uint_as_float(tf32r(Whh[r1*192 + c]));
        PWhh[i] = v;
    }
    if (tid < 64) {
        sbe[tid] = be[tid]; sba[tid] = ba[tid]; sWp[tid] = Wp[tid];
        sbI[tid] = bih[128 + tid]; sbH[tid] = bhh[128 + tid];
    }
    if (tid < 128) sbrz[tid] = bih[tid] + bhh[tid];
    float bpv = bp[0];
    __syncthreads();

    int wid = tid >> 5, lane = tid & 31;
    int rg = wid & 3, cg = wid >> 2;
    int t = lane & 3, g = lane >> 2;
    int rb = rg * 32, cb = cg * 16;
    int q2 = (t >> 1) << 1;
    int l0 = (((g << 2) + ((2*t) & 3)) << 2) + q2;
    int l1 = (((g << 2) + ((2*t + 1)) % 4) << 2) + q2;

    const int NT = NROWS/128;
    int fr[4], fq[4];
    #pragma unroll
    for (int ii = 0; ii < 4; ii++) { int i = tid + ii*512; fr[ii] = i >> 4; fq[ii] = i & 15; }

    float4 pm[4], ph4[4];
    int tile = blockIdx.x;
    if (tile < NT) {
        int row0 = tile << 7;
        #pragma unroll
        for (int ii = 0; ii < 4; ii++) {
            pm[ii]  = *(const float4*)(g_mnext + (size_t)(row0 + fr[ii])*64 + fq[ii]*4);
            ph4[ii] = *(const float4*)(ht      + (size_t)(row0 + fr[ii])*64 + fq[ii]*4);
        }
    }

    for (; tile < NT; tile += gridDim.x) {
        int row0 = tile << 7;

        #pragma unroll
        for (int ii = 0; ii < 4; ii++) {
            int r = fr[ii], q = fq[ii];
            int off = ((((r>>4)<<3) + (q>>1))<<7) + ((r&7)<<4) + ((q&1)<<1) + ((r>>3)&1);
            float* px = Xs + off;
            px[0] = pm[ii].x; px[4] = pm[ii].y; px[8] = pm[ii].z; px[12] = pm[ii].w;
            float* phh = Hs + off;
            phh[0] = tf32f(ph4[ii].x); phh[4] = tf32f(ph4[ii].y);
            phh[8] = tf32f(ph4[ii].z); phh[12] = tf32f(ph4[ii].w);
        }
        __syncthreads();

        int nxt = tile + gridDim.x;
        if (nxt < NT) {
            int nrow0 = nxt << 7;
            #pragma unroll
            for (int ii = 0; ii < 4; ii++) {
                pm[ii]  = *(const float4*)(g_mnext + (size_t)(nrow0 + fr[ii])*64 + fq[ii]*4);
                ph4[ii] = *(const float4*)(ht      + (size_t)(nrow0 + fr[ii])*64 + fq[ii]*4);
            }
        }

        // ---- Phase A ----
        float S[2][2][4], T[2][2][4];
        #pragma unroll
        for (int mt = 0; mt < 2; mt++)
            #pragma unroll
            for (int nt = 0; nt < 2; nt++) {
                int c = cb + nt*8 + 2*t;
                S[mt][nt][0]=sbe[c]; S[mt][nt][1]=sbe[c+1]; S[mt][nt][2]=sbe[c]; S[mt][nt][3]=sbe[c+1];
                T[mt][nt][0]=sba[c]; T[mt][nt][1]=sba[c+1]; T[mt][nt][2]=sba[c]; T[mt][nt][3]=sba[c+1];
            }
        #pragma unroll
        for (int ks = 0; ks < 8; ks++) {
            unsigned f0[4], f1[4];
            ldfragX(f0, Xs, rg*2,     ks, lane);
            ldfragX(f1, Xs, rg*2 + 1, ks, lane);
            #pragma unroll
            for (int nt = 0; nt < 2; nt++) {
                int bi = (ks*8 + cg*2 + nt)*32 + lane;
                float2 bw = PWe[bi];
                unsigned b0 = __float_as_uint(bw.x), b1 = __float_as_uint(bw.y);
                mma8(S[0][nt], f0, b0, b1); mma8(S[1][nt], f1, b0, b1);
                bw = PWa[bi];
                b0 = __float_as_uint(bw.x); b1 = __float_as_uint(bw.y);
                mma8(T[0][nt], f0, b0, b1); mma8(T[1][nt], f1, b0, b1);
            }
        }

        float resv[2][2][4];
        float ga[4];
        #pragma unroll
        for (int q = 0; q < 4; q++)
            ga[q] = ea_w[(row0 + rb + (q>>1)*16 + (q&1)*8 + g) & 1023];
        #pragma unroll
        for (int mt = 0; mt < 2; mt++)
            #pragma unroll
            for (int nt = 0; nt < 2; nt++) {
                const float* base = Xs + ((((rg*2+mt)<<3) + (cg*2+nt))<<7);
                float m00 = base[l0], m01 = base[l1];
                float m10 = base[l0 + 1], m11 = base[l1 + 1];
                float g0 = ga[2*mt], g1 = ga[2*mt+1];
                resv[mt][nt][0] = m00 - g0*sigf(S[mt][nt][0])*m00 + g0*tanhfast(T[mt][nt][0]);
                resv[mt][nt][1] = m01 - g0*sigf(S[mt][nt][1])*m01 + g0*tanhfast(T[mt][nt][1]);
                resv[mt][nt][2] = m10 - g1*sigf(S[mt][nt][2])*m10 + g1*tanhfast(T[mt][nt][2]);
                resv[mt][nt][3] = m11 - g1*sigf(S[mt][nt][3])*m11 + g1*tanhfast(T[mt][nt][3]);
            }
        __syncthreads();
        #pragma unroll
        for (int mt = 0; mt < 2; mt++)
            #pragma unroll
            for (int nt = 0; nt < 2; nt++) {
                float* base = Xs + ((((rg*2+mt)<<3) + (cg*2+nt))<<7);
                base[l0]     = tf32f(resv[mt][nt][0]);
                base[l1]     = tf32f(resv[mt][nt][1]);
                base[l0 + 1] = tf32f(resv[mt][nt][2]);
                base[l1 + 1] = tf32f(resv[mt][nt][3]);
            }
        __syncthreads();

        // ---- Phase BC ----
        float R[2][2][4], Z[2][2][4], I_[2][2][4], Hh[2][2][4];
        #pragma unroll
        for (int mt = 0; mt < 2; mt++)
            #pragma unroll
            for (int nt = 0; nt < 2; nt++) {
                int c = cb + nt*8 + 2*t;
                R[mt][nt][0]=sbrz[c];    R[mt][nt][1]=sbrz[c+1];    R[mt][nt][2]=sbrz[c];    R[mt][nt][3]=sbrz[c+1];
                Z[mt][nt][0]=sbrz[64+c]; Z[mt][nt][1]=sbrz[64+c+1]; Z[mt][nt][2]=sbrz[64+c]; Z[mt][nt][3]=sbrz[64+c+1];
                I_[mt][nt][0]=sbI[c];    I_[mt][nt][1]=sbI[c+1];    I_[mt][nt][2]=sbI[c];    I_[mt][nt][3]=sbI[c+1];
                Hh[mt][nt][0]=sbH[c];    Hh[mt][nt][1]=sbH[c+1];    Hh[mt][nt][2]=sbH[c];    Hh[mt][nt][3]=sbH[c+1];
            }
        #pragma unroll
        for (int ks = 0; ks < 8; ks++) {
            unsigned f0[4], f1[4];
            ldfragX(f0, Xs, rg*2,     ks, lane);
            ldfragX(f1, Xs, rg*2 + 1, ks, lane);
            #pragma unroll
            for (int nt = 0; nt < 2; nt++) {
                int bi = (ks*24 + cg*2 + nt)*32 + lane;
                float2 bw = PWih[bi];
                unsigned b0 = __float_as_uint(bw.x), b1 = __float_as_uint(bw.y);
                mma8(R[0][nt], f0, b0, b1); mma8(R[1][nt], f1, b0, b1);
                bw = PWih[bi + 256];
                b0 = __float_as_uint(bw.x); b1 = __float_as_uint(bw.y);
                mma8(Z[0][nt], f0, b0, b1); mma8(Z[1][nt], f1, b0, b1);
                bw = PWih[bi + 512];
                b0 = __float_as_uint(bw.x); b1 = __float_as_uint(bw.y);
                mma8(I_[0][nt], f0, b0, b1); mma8(I_[1][nt], f1, b0, b1);
            }
            ldfragX(f0, Hs, rg*2,     ks, lane);
            ldfragX(f1, Hs, rg*2 + 1, ks, lane);
            #pragma unroll
            for (int nt = 0; nt < 2; nt++) {
                int bi = (ks*24 + cg*2 + nt)*32 + lane;
                float2 bw = PWhh[bi];
                unsigned b0 = __float_as_uint(bw.x), b1 = __float_as_uint(bw.y);
                mma8(R[0][nt], f0, b0, b1); mma8(R[1][nt], f1, b0, b1);
                bw = PWhh[bi + 256];
                b0 = __float_as_uint(bw.x); b1 = __float_as_uint(bw.y);
                mma8(Z[0][nt], f0, b0, b1); mma8(Z[1][nt], f1, b0, b1);
                bw = PWhh[bi + 512];
                b0 = __float_as_uint(bw.x); b1 = __float_as_uint(bw.y);
                mma8(Hh[0][nt], f0, b0, b1); mma8(Hh[1][nt], f1, b0, b1);
            }
        }

        float py[4] = {0.f, 0.f, 0.f, 0.f};
        #pragma unroll
        for (int mt = 0; mt < 2; mt++)
            #pragma unroll
            for (int nt = 0; nt < 2; nt++) {
                int c = cb + nt*8 + 2*t;
                const float* hbase = Hs + ((((rg*2+mt)<<3) + (cg*2+nt))<<7);
                float h00 = hbase[l0], h01 = hbase[l1];
                float h10 = hbase[l0 + 1], h11 = hbase[l1 + 1];
                float wc0 = sWp[c], wc1 = sWp[c+1];
                {
                    float rr = sigf(R[mt][nt][0]), zz = sigf(Z[mt][nt][0]);
                    float nn = tanhfast(I_[mt][nt][0] + rr*Hh[mt][nt][0]);
                    py[2*mt] = fmaf((1.f-zz)*nn + zz*h00, wc0, py[2*mt]);
                }
                {
                    float rr = sigf(R[mt][nt][1]), zz = sigf(Z[mt][nt][1]);
                    float nn = tanhfast(I_[mt][nt][1] + rr*Hh[mt][nt][1]);
                    py[2*mt] = fmaf((1.f-zz)*nn + zz*h01, wc1, py[2*mt]);
                }
                {
                    float rr = sigf(R[mt][nt][2]), zz = sigf(Z[mt][nt][2]);
                    float nn = tanhfast(I_[mt][nt][2] + rr*Hh[mt][nt][2]);
                    py[2*mt+1] = fmaf((1.f-zz)*nn + zz*h10, wc0, py[2*mt+1]);
                }
                {
                    float rr = sigf(R[mt][nt][3]), zz = sigf(Z[mt][nt][3]);
                    float nn = tanhfast(I_[mt][nt][3] + rr*Hh[mt][nt][3]);
                    py[2*mt+1] = fmaf((1.f-zz)*nn + zz*h11, wc1, py[2*mt+1]);
                }
            }
        #pragma unroll
        for (int q = 0; q < 4; q++) {
            py[q] += __shfl_xor_sync(0xffffffffu, py[q], 1, 4);
            py[q] += __shfl_xor_sync(0xffffffffu, py[q], 2, 4);
        }
        if (t == 0) {
            sred[cg*128 + rb + g]      = py[0];
            sred[cg*128 + rb + 8 + g]  = py[1];
            sred[cg*128 + rb + 16 + g] = py[2];
            sred[cg*128 + rb + 24 + g] = py[3];
        }
        __syncthreads();
        if (tid < 128)
            out[row0 + tid] = sigf(sred[tid] + sred[128+tid] + sred[256+tid] + sred[384+tid] + bpv);
        __syncthreads();
    }
}

// ---------------------------------------------------------------------------
extern "C" void kernel_launch(void* const* d_in, const int* in_sizes, int n_in,
                              void* d_out, int out_size)
{
    const int*   qt  = (const int*)  d_in[1];
    const float* ht  = (const float*)d_in[2];
    const float* oh  = (const float*)d_in[3];
    const float* kc  = (const float*)d_in[4];
    const float* gr  = (const float*)d_in[5];
    const float* nw  = (const float*)d_in[6];
    const float* Ws1 = (const float*)d_in[7];
    const float* bs1 = (const float*)d_in[8];
    const float* Ws2 = (const float*)d_in[9];
    const float* bs2 = (const float*)d_in[10];
    const float* Wn1 = (const float*)d_in[11];
    const float* bn1 = (const float*)d_in[12];
    const float* Wn2 = (const float*)d_in[13];
    const float* bn2 = (const float*)d_in[14];
    const float* ea  = (const float*)d_in[15];
    const float* We  = (const float*)d_in[16];
    const float* be  = (const float*)d_in[17];
    const float* Wa  = (const float*)d_in[18];
    const float* ba  = (const float*)d_in[19];
    const float* Wih = (const float*)d_in[20];
    const float* bih = (const float*)d_in[21];
    const float* Whh = (const float*)d_in[22];
    const float* bhh = (const float*)d_in[23];
    const float* Wp  = (const float*)d_in[24];
    const float* bp  = (const float*)d_in[25];
    float* out = (float*)d_out;

    int smc = 148;
    if (cudaDeviceGetAttribute(&smc, cudaDevAttrMultiProcessorCount, 0) != cudaSuccess || smc <= 0)
        smc = 148;

    size_t smem1 = (size_t)(8192 + 16384 + 8192 + 8192 + 128 + 256) * 4;   // 165,376 B
    size_t smem2 = (size_t)(8192 + 8192 + 4096 + 4096 + 12288 + 12288 + 64+64+128+64+64+64+512) * 4;  // 200,448 B
    cudaFuncSetAttribute(f1_kernel, cudaFuncAttributeMaxDynamicSharedMemorySize, (int)smem1);
    cudaFuncSetAttribute(f2_kernel, cudaFuncAttributeMaxDynamicSharedMemorySize, (int)smem2);

    adj_kernel<<<1, 1024>>>(qt, oh, gr);
    maskscan_kernel<<<256, 256>>>(qt, oh);
    kcbase_kernel<<<1024, 128>>>(kc, Wn1, bn1);
    f1_kernel<<<smc, 512, smem1>>>(ht, nw, Wn1, Wn2, bn2);
    selfmlp_kernel<<<2048, 128>>>(ht, kc, Ws1, bs1, Ws2, bs2);
    f2_kernel<<<smc, 512, smem2>>>(ht, ea, We, be, Wa, ba, Wih, bih, Whh, bhh, Wp, bp, out);
}

// round 13
// speedup vs baseline: 1.6348x; 1.5321x over previous
#include <cuda_runtime.h>
#include <cuda_fp16.h>
#include <cstdint>
#include <math.h>

#define CC 1024
#define NROWS (256*1024)

// Scratch (allocation-free rule: __device__ globals)
__device__ float    g_adj[2*CC];
__device__ float    g_kcbase[2*CC*64];
__device__ unsigned g_mnexth[(size_t)NROWS * 32];   // half2 packed, 32 MB
__device__ int      g_mcnt;
__device__ int      g_mlist[65536];

__device__ __forceinline__ float clampf(float v,float lo,float hi){ return fminf(fmaxf(v,lo),hi); }
__device__ __forceinline__ float sigf(float x){ return __fdividef(1.f, 1.f + __expf(-x)); }
__device__ __forceinline__ float tanhfast(float x){
    float t = __expf(-2.f*fabsf(x));
    float r = __fdividef(1.f - t, 1.f + t);
    return copysignf(r, x);
}

// ---- fp16 helpers -----------------------------------------------------------
__device__ __forceinline__ unsigned pk_h2(float lo, float hi){
    __half2 h = __floats2half2_rn(lo, hi);
    return *reinterpret_cast<unsigned*>(&h);
}
__device__ __forceinline__ float2 up_h2(unsigned u){
    __half2 h = *reinterpret_cast<__half2*>(&u);
    return __half22float2(h);
}
// m16n8k16 f16 mma, fp32 accum. C layout: c0=(g,2t) c1=(g,2t+1) c2=(g+8,2t) c3=(g+8,2t+1)
__device__ __forceinline__ void mmaf16(float c[4], const unsigned a[4], unsigned b0, unsigned b1){
    asm volatile(
        "mma.sync.aligned.m16n8k16.row.col.f32.f16.f16.f32 "
        "{%0,%1,%2,%3},{%4,%5,%6,%7},{%8,%9},{%0,%1,%2,%3};"
        : "+f"(c[0]),"+f"(c[1]),"+f"(c[2]),"+f"(c[3])
        : "r"(a[0]),"r"(a[1]),"r"(a[2]),"r"(a[3]),"r"(b0),"r"(b1));
}
// A fragment (16 rows x 16 k) from fragment-major half2 smem: one LDS.128.
// Layout: X[((rowblk*4+ks)<<7) + lane*4 + reg] (u32 units)
__device__ __forceinline__ void ldfragH(unsigned a[4], const unsigned* X, int rowblk, int ks, int lane){
    uint4 v = *(const uint4*)(X + (((rowblk<<2) + ks)<<7) + (lane<<2));
    a[0]=v.x; a[1]=v.y; a[2]=v.z; a[3]=v.w;
}

// ---------------------------------------------------------------------------
// adj: mask0 has ~5 nonzeros -> compact + gather. Also resets g_mcnt.
// ---------------------------------------------------------------------------
__global__ void adj_kernel(const int* __restrict__ qt,
                           const float* __restrict__ oh,
                           const float* __restrict__ graphs)
{
    __shared__ int   s_idx[CC];
    __shared__ float s_val[CC];
    __shared__ int   s_cnt;
    __shared__ float s_sum;

    int t = threadIdx.x;
    if (t == 0) { s_cnt = 0; s_sum = 0.f; g_mcnt = 0; }
    __syncthreads();

    int q0 = qt[0];
    float m = oh[(size_t)q0 * CC + t];
    if (m != 0.f) {
        int p = atomicAdd(&s_cnt, 1);
        s_idx[p] = t; s_val[p] = m;
        atomicAdd(&s_sum, m);
    }
    __syncthreads();

    float denom = fmaxf(s_sum, 1.f);
    int nnz = s_cnt;
    for (int k = 0; k < 2; k++) {
        float acc = 0.f;
        for (int i = 0; i < nnz; i++)
            acc += s_val[i] * graphs[(size_t)k*CC*CC + (size_t)s_idx[i]*CC + t];
        g_adj[k*CC + t] = clampf(acc / denom, -5.f, 5.f);
    }
}

__global__ void maskscan_kernel(const int* __restrict__ qt,
                                const float* __restrict__ oh)
{
    int b = blockIdx.x;
    int q = qt[b];
    for (int c = threadIdx.x; c < CC; c += blockDim.x) {
        if (oh[(size_t)q*CC + c] > 0.5f) {
            int p = atomicAdd(&g_mcnt, 1);
            if (p < 65536) g_mlist[p] = (b << 16) | c;
        }
    }
}

__global__ void kcbase_kernel(const float* __restrict__ kc,
                              const float* __restrict__ Wn1,
                              const float* __restrict__ bn1)
{
    __shared__ float skc[64];
    int c = blockIdx.x;
    int tid = threadIdx.x;              // 128
    if (tid < 64) skc[tid] = clampf(kc[c*64 + tid], -5.f, 5.f);
    __syncthreads();
    int k = tid >> 6, j = tid & 63;
    float a = bn1[k*64 + j];
    const float* Wp = Wn1 + k*16384 + 12288 + j;
    #pragma unroll 8
    for (int e = 0; e < 64; e++) a = fmaf(skc[e], Wp[e*64], a);
    g_kcbase[((size_t)k*CC + c)*64 + j] = a;
}

// ---------------------------------------------------------------------------
// f1 (fp16 tensor): 128-row tiles, 512 threads, 2 blocks/SM.
// ---------------------------------------------------------------------------
__global__ void __launch_bounds__(512, 2) f1_kernel(
    const float* __restrict__ ht,  const float* __restrict__ nwp,
    const float* __restrict__ Wn1, const float* __restrict__ Wn2,
    const float* __restrict__ bn2)
{
    extern __shared__ unsigned smu[];
    unsigned* Xs   = smu;                 // 4096 u32 (clip(ht) fp16 frag-major)
    unsigned* H1s  = Xs + 4096;           // 2*4096
    uint2*    PW1  = (uint2*)(H1s + 8192);// 2048 uint2
    uint2*    PW2  = PW1 + 2048;          // 2048 uint2
    float*    sbn2 = (float*)(PW2 + 2048);// 128
    float*    radj = sbn2 + 128;          // 256

    int tid = threadIdx.x;
    for (int i = tid; i < 2048; i += 512) {
        int lane = i & 31, nt = (i>>5)&7, ks = (i>>8)&3, k = i>>10;
        int t = lane & 3, g = lane >> 2;
        int c = nt*8 + g;
        int r0 = ks*16 + 2*t;
        const float* W1p = Wn1 + k*16384 + 128*64;   // ht-part rows 128..191
        uint2 w;
        w.x = pk_h2(W1p[r0*64 + c],     W1p[(r0+1)*64 + c]);
        w.y = pk_h2(W1p[(r0+8)*64 + c], W1p[(r0+9)*64 + c]);
        PW1[i] = w;
        const float* W2p = Wn2 + k*4096;
        w.x = pk_h2(W2p[r0*64 + c],     W2p[(r0+1)*64 + c]);
        w.y = pk_h2(W2p[(r0+8)*64 + c], W2p[(r0+9)*64 + c]);
        PW2[i] = w;
    }
    if (tid < 128) sbn2[tid] = bn2[tid];
    float w = clampf(nwp[0], 0.1f, 0.9f);
    __syncthreads();

    int wid = tid >> 5, lane = tid & 31;
    int rg = wid & 3, cg = wid >> 2;     // 4 x 4
    int t = lane & 3, g = lane >> 2;
    int rb = rg * 32, cb = cg * 16;

    for (int tile = blockIdx.x; tile < NROWS/128; tile += gridDim.x) {
        int row0 = tile << 7;
        int c0 = row0 & 1023;

        // fill Xs = fp16(clip(ht)) fragment-major
        for (int i = tid; i < 2048; i += 512) {
            int r = i >> 4, q = i & 15;
            float4 v = *(const float4*)(ht + (size_t)(row0+r)*64 + q*4);
            int ks = q >> 2;
            int reg = ((q >> 1) & 1)*2 + ((r >> 3) & 1);
            int base = (((r >> 4)*4 + ks) << 7) + reg;
            int la0 = (r & 7)*4 + ((2*q) & 3);
            int la1 = (r & 7)*4 + ((2*q + 1) & 3);
            Xs[base + la0*4] = pk_h2(clampf(v.x,-5.f,5.f), clampf(v.y,-5.f,5.f));
            Xs[base + la1*4] = pk_h2(clampf(v.z,-5.f,5.f), clampf(v.w,-5.f,5.f));
        }
        if (tid < 128) {
            int c = (row0 + tid) & 1023;
            radj[tid]       = g_adj[c];
            radj[128 + tid] = g_adj[CC + c];
        }
        __syncthreads();

        // ---- Stage A (both k): acc init from kcbase (fp32) ----
        float A[2][2][2][4];
        #pragma unroll
        for (int k = 0; k < 2; k++) {
            const float* kcb = g_kcbase + ((size_t)k*CC + c0)*64;
            #pragma unroll
            for (int mt = 0; mt < 2; mt++)
                #pragma unroll
                for (int nt = 0; nt < 2; nt++) {
                    int c = cb + nt*8 + 2*t;
                    int rA = rb + mt*16 + g;
                    float2 v0 = *(const float2*)(kcb + rA*64 + c);
                    float2 v1 = *(const float2*)(kcb + (rA+8)*64 + c);
                    A[k][mt][nt][0]=v0.x; A[k][mt][nt][1]=v0.y;
                    A[k][mt][nt][2]=v1.x; A[k][mt][nt][3]=v1.y;
                }
        }
        #pragma unroll
        for (int ks = 0; ks < 4; ks++) {
            unsigned f0[4], f1v[4];
            ldfragH(f0,  Xs, rg*2,     ks, lane);
            ldfragH(f1v, Xs, rg*2 + 1, ks, lane);
            #pragma unroll
            for (int k = 0; k < 2; k++)
                #pragma unroll
                for (int nt = 0; nt < 2; nt++) {
                    uint2 bw = PW1[((k*4 + ks)*8 + cg*2 + nt)*32 + lane];
                    mmaf16(A[k][0][nt], f0,  bw.x, bw.y);
                    mmaf16(A[k][1][nt], f1v, bw.x, bw.y);
                }
        }
        // relu -> H1s (fp16, frag-major) via STS.64
        #pragma unroll
        for (int k = 0; k < 2; k++) {
            unsigned* Hk = H1s + k*4096;
            #pragma unroll
            for (int mt = 0; mt < 2; mt++)
                #pragma unroll
                for (int nt = 0; nt < 2; nt++) {
                    int off = (((rg*2+mt)*4 + cg) << 7) + (g*4 + t)*4 + nt*2;
                    uint2 st;
                    st.x = pk_h2(fmaxf(A[k][mt][nt][0],0.f), fmaxf(A[k][mt][nt][1],0.f));
                    st.y = pk_h2(fmaxf(A[k][mt][nt][2],0.f), fmaxf(A[k][mt][nt][3],0.f));
                    *(uint2*)(Hk + off) = st;
                }
        }
        __syncthreads();

        // ---- Stage B (both k) ----
        float B[2][2][2][4];
        #pragma unroll
        for (int k = 0; k < 2; k++)
            #pragma unroll
            for (int mt = 0; mt < 2; mt++)
                #pragma unroll
                for (int nt = 0; nt < 2; nt++) {
                    int c = cb + nt*8 + 2*t;
                    float b0 = sbn2[k*64 + c], b1 = sbn2[k*64 + c + 1];
                    B[k][mt][nt][0]=b0; B[k][mt][nt][1]=b1; B[k][mt][nt][2]=b0; B[k][mt][nt][3]=b1;
                }
        #pragma unroll
        for (int ks = 0; ks < 4; ks++) {
            #pragma unroll
            for (int k = 0; k < 2; k++) {
                unsigned e0[4], e1[4];
                ldfragH(e0, H1s + k*4096, rg*2,     ks, lane);
                ldfragH(e1, H1s + k*4096, rg*2 + 1, ks, lane);
                #pragma unroll
                for (int nt = 0; nt < 2; nt++) {
                    uint2 bw = PW2[((k*4 + ks)*8 + cg*2 + nt)*32 + lane];
                    mmaf16(B[k][0][nt], e0, bw.x, bw.y);
                    mmaf16(B[k][1][nt], e1, bw.x, bw.y);
                }
            }
        }

        // fold nf + write ALL rows as half2 pairs
        #pragma unroll
        for (int mt = 0; mt < 2; mt++) {
            int rA = rb + mt*16 + g;
            float a00 = radj[rA],       a01 = radj[rA + 8];
            float a10 = radj[128 + rA], a11 = radj[128 + rA + 8];
            #pragma unroll
            for (int nt = 0; nt < 2; nt++) {
                int c = cb + nt*8 + 2*t;
                float n0 = clampf(a00 * clampf(B[0][mt][nt][0], 0.f, 5.f), -5.f, 5.f);
                float n1 = clampf(a00 * clampf(B[0][mt][nt][1], 0.f, 5.f), -5.f, 5.f);
                float n2 = clampf(a01 * clampf(B[0][mt][nt][2], 0.f, 5.f), -5.f, 5.f);
                float n3 = clampf(a01 * clampf(B[0][mt][nt][3], 0.f, 5.f), -5.f, 5.f);
                float u0 = a10 * clampf(B[1][mt][nt][0], 0.f, 5.f);
                float u1 = a10 * clampf(B[1][mt][nt][1], 0.f, 5.f);
                float u2 = a11 * clampf(B[1][mt][nt][2], 0.f, 5.f);
                float u3 = a11 * clampf(B[1][mt][nt][3], 0.f, 5.f);
                n0 = clampf(w*n0 + (1.f-w)*u0, -5.f, 5.f);
                n1 = clampf(w*n1 + (1.f-w)*u1, -5.f, 5.f);
                n2 = clampf(w*n2 + (1.f-w)*u2, -5.f, 5.f);
                n3 = clampf(w*n3 + (1.f-w)*u3, -5.f, 5.f);
                g_mnexth[(size_t)(row0+rA)*32   + (c>>1)] = pk_h2(n0, n1);
                g_mnexth[(size_t)(row0+rA+8)*32 + (c>>1)] = pk_h2(n2, n3);
            }
        }
        __syncthreads();
    }
}

// ---------------------------------------------------------------------------
// selfmlp fix: one masked (b,c) pair per block (exact fp32 then fp16 store)
// ---------------------------------------------------------------------------
__global__ void __launch_bounds__(128) selfmlp_kernel(
    const float* __restrict__ ht, const float* __restrict__ kc,
    const float* __restrict__ Ws1, const float* __restrict__ bs1,
    const float* __restrict__ Ws2, const float* __restrict__ bs2)
{
    __shared__ float xr[128];
    __shared__ float hb[64];
    __shared__ float sout[64];
    int tid = threadIdx.x;
    int cnt = g_mcnt; if (cnt > 65536) cnt = 65536;

    for (int i = blockIdx.x; i < cnt; i += gridDim.x) {
        int pc = g_mlist[i];
        int b = pc >> 16, c = pc & 0xffff;
        size_t gid = (size_t)b*CC + c;
        xr[tid] = (tid < 64) ? ht[gid*64 + tid] : kc[c*64 + tid - 64];
        __syncthreads();
        if (tid < 64) {
            float a = bs1[tid];
            #pragma unroll 8
            for (int j = 0; j < 128; j++) a = fmaf(xr[j], Ws1[j*64 + tid], a);
            hb[tid] = fmaxf(a, 0.f);
        }
        __syncthreads();
        if (tid < 64) {
            float a = bs2[tid];
            #pragma unroll 8
            for (int j = 0; j < 64; j++) a = fmaf(hb[j], Ws2[j*64 + tid], a);
            sout[tid] = clampf(a, 0.f, 10.f);
        }
        __syncthreads();
        if (tid < 32)
            g_mnexth[gid*32 + tid] = pk_h2(sout[2*tid], sout[2*tid+1]);
        __syncthreads();
    }
}

// ---------------------------------------------------------------------------
// f2 (fp16 tensor): 128-row tiles, 512 threads, register-prefetched fills.
// ---------------------------------------------------------------------------
__global__ void __launch_bounds__(512) f2_kernel(
    const float* __restrict__ ht,  const float* __restrict__ ea_w,
    const float* __restrict__ We,  const float* __restrict__ be,
    const float* __restrict__ Wa,  const float* __restrict__ ba,
    const float* __restrict__ Wih, const float* __restrict__ bih,
    const float* __restrict__ Whh, const float* __restrict__ bhh,
    const float* __restrict__ Wp,  const float* __restrict__ bp,
    float* __restrict__ out)
{
    extern __shared__ unsigned smu[];
    unsigned* Xs   = smu;                  // 4096 u32 (m fp16 -> res fp16)
    unsigned* Hs   = Xs + 4096;            // 4096 u32 (ht fp16)
    uint2*    PWe  = (uint2*)(Hs + 4096);  // 1024 uint2
    uint2*    PWa  = PWe + 1024;           // 1024
    uint2*    PWih = PWa + 1024;           // 3072
    uint2*    PWhh = PWih + 3072;          // 3072
    float*    sbe  = (float*)(PWhh + 3072);
    float*    sba  = sbe + 64;
    float*    sbrz = sba + 64;             // 128
    float*    sbI  = sbrz + 128;
    float*    sbH  = sbI + 64;
    float*    sWp  = sbH + 64;
    float*    sred = sWp + 64;             // 512

    int tid = threadIdx.x;

    for (int i = tid; i < 1024; i += 512) {
        int lane = i & 31, nt = (i>>5)&7, ks = i>>8;
        int t = lane & 3, g = lane >> 2;
        int c = nt*8 + g;
        int r0 = ks*16 + 2*t;
        uint2 w;
        w.x = pk_h2(We[r0*64 + c],     We[(r0+1)*64 + c]);
        w.y = pk_h2(We[(r0+8)*64 + c], We[(r0+9)*64 + c]);
        PWe[i] = w;
        w.x = pk_h2(Wa[r0*64 + c],     Wa[(r0+1)*64 + c]);
        w.y = pk_h2(Wa[(r0+8)*64 + c], Wa[(r0+9)*64 + c]);
        PWa[i] = w;
    }
    for (int i = tid; i < 3072; i += 512) {
        int lane = i & 31; int rest = i >> 5; int sub = rest % 24, ks = rest / 24;
        int t = lane & 3, g = lane >> 2;
        int c = sub*8 + g;
        int r0 = ks*16 + 2*t;
        uint2 w;
        w.x = pk_h2(Wih[r0*192 + c],     Wih[(r0+1)*192 + c]);
        w.y = pk_h2(Wih[(r0+8)*192 + c], Wih[(r0+9)*192 + c]);
        PWih[i] = w;
        w.x = pk_h2(Whh[r0*192 + c],     Whh[(r0+1)*192 + c]);
        w.y = pk_h2(Whh[(r0+8)*192 + c], Whh[(r0+9)*192 + c]);
        PWhh[i] = w;
    }
    if (tid < 64) {
        sbe[tid] = be[tid]; sba[tid] = ba[tid]; sWp[tid] = Wp[tid];
        sbI[tid] = bih[128 + tid]; sbH[tid] = bhh[128 + tid];
    }
    if (tid < 128) sbrz[tid] = bih[tid] + bhh[tid];
    float bpv = bp[0];
    __syncthreads();

    int wid = tid >> 5, lane = tid & 31;
    int rg = wid & 3, cg = wid >> 2;
    int t = lane & 3, g = lane >> 2;
    int rb = rg * 32, cb = cg * 16;

    const int NT = NROWS/128;
    // fill indices: pm (half2 m rows): 2 chunks; ph (ht float4): 4 chunks
    int mr[2], mq[2], hr[4], hq[4];
    #pragma unroll
    for (int ii = 0; ii < 2; ii++) { int i = tid + ii*512; mr[ii] = i >> 3; mq[ii] = i & 7; }
    #pragma unroll
    for (int ii = 0; ii < 4; ii++) { int i = tid + ii*512; hr[ii] = i >> 4; hq[ii] = i & 15; }

    uint4 pm[2]; float4 ph[4];
    int tile = blockIdx.x;
    if (tile < NT) {
        int row0 = tile << 7;
        #pragma unroll
        for (int ii = 0; ii < 2; ii++)
            pm[ii] = *(const uint4*)(g_mnexth + (size_t)(row0 + mr[ii])*32 + mq[ii]*4);
        #pragma unroll
        for (int ii = 0; ii < 4; ii++)
            ph[ii] = *(const float4*)(ht + (size_t)(row0 + hr[ii])*64 + hq[ii]*4);
    }

    for (; tile < NT; tile += gridDim.x) {
        int row0 = tile << 7;

        // store prefetched m (already fp16 half2) into Xs frag-major
        #pragma unroll
        for (int ii = 0; ii < 2; ii++) {
            int r = mr[ii], q = mq[ii];
            int ks = q >> 1;
            int regb = (q & 1)*2 + ((r >> 3) & 1);
            int base = (((r >> 4)*4 + ks) << 7) + regb;
            int lb = (r & 7)*4;
            Xs[base + (lb+0)*4] = pm[ii].x;
            Xs[base + (lb+1)*4] = pm[ii].y;
            Xs[base + (lb+2)*4] = pm[ii].z;
            Xs[base + (lb+3)*4] = pm[ii].w;
        }
        // store prefetched ht into Hs frag-major (fp16)
        #pragma unroll
        for (int ii = 0; ii < 4; ii++) {
            int r = hr[ii], q = hq[ii];
            float4 v = ph[ii];
            int ks = q >> 2;
            int reg = ((q >> 1) & 1)*2 + ((r >> 3) & 1);
            int base = (((r >> 4)*4 + ks) << 7) + reg;
            int la0 = (r & 7)*4 + ((2*q) & 3);
            int la1 = (r & 7)*4 + ((2*q + 1) & 3);
            Hs[base + la0*4] = pk_h2(v.x, v.y);
            Hs[base + la1*4] = pk_h2(v.z, v.w);
        }
        __syncthreads();

        int nxt = tile + gridDim.x;
        if (nxt < NT) {
            int nrow0 = nxt << 7;
            #pragma unroll
            for (int ii = 0; ii < 2; ii++)
                pm[ii] = *(const uint4*)(g_mnexth + (size_t)(nrow0 + mr[ii])*32 + mq[ii]*4);
            #pragma unroll
            for (int ii = 0; ii < 4; ii++)
                ph[ii] = *(const float4*)(ht + (size_t)(nrow0 + hr[ii])*64 + hq[ii]*4);
        }

        // ---- Phase A: S = m@We+be, T = m@Wa+ba ----
        float S[2][2][4], T[2][2][4];
        #pragma unroll
        for (int mt = 0; mt < 2; mt++)
            #pragma unroll
            for (int nt = 0; nt < 2; nt++) {
                int c = cb + nt*8 + 2*t;
                S[mt][nt][0]=sbe[c]; S[mt][nt][1]=sbe[c+1]; S[mt][nt][2]=sbe[c]; S[mt][nt][3]=sbe[c+1];
                T[mt][nt][0]=sba[c]; T[mt][nt][1]=sba[c+1]; T[mt][nt][2]=sba[c]; T[mt][nt][3]=sba[c+1];
            }
        #pragma unroll
        for (int ks = 0; ks < 4; ks++) {
            unsigned f0[4], f1[4];
            ldfragH(f0, Xs, rg*2,     ks, lane);
            ldfragH(f1, Xs, rg*2 + 1, ks, lane);
            #pragma unroll
            for (int nt = 0; nt < 2; nt++) {
                uint2 bw = PWe[(ks*8 + cg*2 + nt)*32 + lane];
                mmaf16(S[0][nt], f0, bw.x, bw.y); mmaf16(S[1][nt], f1, bw.x, bw.y);
                bw = PWa[(ks*8 + cg*2 + nt)*32 + lane];
                mmaf16(T[0][nt], f0, bw.x, bw.y); mmaf16(T[1][nt], f1, bw.x, bw.y);
            }
        }

        // res = m - g*sig(S)*m + g*tanh(T)
        float resv[2][2][4];
        float ga[4];
        #pragma unroll
        for (int q = 0; q < 4; q++)
            ga[q] = ea_w[(row0 + rb + (q>>1)*16 + (q&1)*8 + g) & 1023];
        #pragma unroll
        for (int mt = 0; mt < 2; mt++)
            #pragma unroll
            for (int nt = 0; nt < 2; nt++) {
                int off = (((rg*2+mt)*4 + cg) << 7) + (g*4 + t)*4 + nt*2;
                float2 m0 = up_h2(Xs[off]);       // row g, cols 2t,2t+1
                float2 m1 = up_h2(Xs[off + 1]);   // row g+8
                float g0 = ga[2*mt], g1 = ga[2*mt+1];
                resv[mt][nt][0] = m0.x - g0*sigf(S[mt][nt][0])*m0.x + g0*tanhfast(T[mt][nt][0]);
                resv[mt][nt][1] = m0.y - g0*sigf(S[mt][nt][1])*m0.y + g0*tanhfast(T[mt][nt][1]);
                resv[mt][nt][2] = m1.x - g1*sigf(S[mt][nt][2])*m1.x + g1*tanhfast(T[mt][nt][2]);
                resv[mt][nt][3] = m1.y - g1*sigf(S[mt][nt][3])*m1.y + g1*tanhfast(T[mt][nt][3]);
            }
        __syncthreads();
        #pragma unroll
        for (int mt = 0; mt < 2; mt++)
            #pragma unroll
            for (int nt = 0; nt < 2; nt++) {
                int off = (((rg*2+mt)*4 + cg) << 7) + (g*4 + t)*4 + nt*2;
                uint2 st;
                st.x = pk_h2(resv[mt][nt][0], resv[mt][nt][1]);
                st.y = pk_h2(resv[mt][nt][2], resv[mt][nt][3]);
                *(uint2*)(Xs + off) = st;
            }
        __syncthreads();

        // ---- Phase BC: R,Z (res+ht), I (res), H (ht) ----
        float R[2][2][4], Z[2][2][4], I_[2][2][4], Hh[2][2][4];
        #pragma unroll
        for (int mt = 0; mt < 2; mt++)
            #pragma unroll
            for (int nt = 0; nt < 2; nt++) {
                int c = cb + nt*8 + 2*t;
                R[mt][nt][0]=sbrz[c];    R[mt][nt][1]=sbrz[c+1];    R[mt][nt][2]=sbrz[c];    R[mt][nt][3]=sbrz[c+1];
                Z[mt][nt][0]=sbrz[64+c]; Z[mt][nt][1]=sbrz[64+c+1]; Z[mt][nt][2]=sbrz[64+c]; Z[mt][nt][3]=sbrz[64+c+1];
                I_[mt][nt][0]=sbI[c];    I_[mt][nt][1]=sbI[c+1];    I_[mt][nt][2]=sbI[c];    I_[mt][nt][3]=sbI[c+1];
                Hh[mt][nt][0]=sbH[c];    Hh[mt][nt][1]=sbH[c+1];    Hh[mt][nt][2]=sbH[c];    Hh[mt][nt][3]=sbH[c+1];
            }
        #pragma unroll
        for (int ks = 0; ks < 4; ks++) {
            unsigned f0[4], f1[4];
            ldfragH(f0, Xs, rg*2,     ks, lane);
            ldfragH(f1, Xs, rg*2 + 1, ks, lane);
            #pragma unroll
            for (int nt = 0; nt < 2; nt++) {
                int bi = (ks*24 + cg*2 + nt)*32 + lane;
                uint2 bw = PWih[bi];
                mmaf16(R[0][nt], f0, bw.x, bw.y); mmaf16(R[1][nt], f1, bw.x, bw.y);
                bw = PWih[bi + 256];
                mmaf16(Z[0][nt], f0, bw.x, bw.y); mmaf16(Z[1][nt], f1, bw.x, bw.y);
                bw = PWih[bi + 512];
                mmaf16(I_[0][nt], f0, bw.x, bw.y); mmaf16(I_[1][nt], f1, bw.x, bw.y);
            }
            ldfragH(f0, Hs, rg*2,     ks, lane);
            ldfragH(f1, Hs, rg*2 + 1, ks, lane);
            #pragma unroll
            for (int nt = 0; nt < 2; nt++) {
                int bi = (ks*24 + cg*2 + nt)*32 + lane;
                uint2 bw = PWhh[bi];
                mmaf16(R[0][nt], f0, bw.x, bw.y); mmaf16(R[1][nt], f1, bw.x, bw.y);
                bw = PWhh[bi + 256];
                mmaf16(Z[0][nt], f0, bw.x, bw.y); mmaf16(Z[1][nt], f1, bw.x, bw.y);
                bw = PWhh[bi + 512];
                mmaf16(Hh[0][nt], f0, bw.x, bw.y); mmaf16(Hh[1][nt], f1, bw.x, bw.y);
            }
        }

        // ---- epilogue ----
        float py[4] = {0.f, 0.f, 0.f, 0.f};
        #pragma unroll
        for (int mt = 0; mt < 2; mt++)
            #pragma unroll
            for (int nt = 0; nt < 2; nt++) {
                int c = cb + nt*8 + 2*t;
                int off = (((rg*2+mt)*4 + cg) << 7) + (g*4 + t)*4 + nt*2;
                float2 h0 = up_h2(Hs[off]);
                float2 h1 = up_h2(Hs[off + 1]);
                float wc0 = sWp[c], wc1 = sWp[c+1];
                {
                    float rr = sigf(R[mt][nt][0]), zz = sigf(Z[mt][nt][0]);
                    float nn = tanhfast(I_[mt][nt][0] + rr*Hh[mt][nt][0]);
                    py[2*mt] = fmaf((1.f-zz)*nn + zz*h0.x, wc0, py[2*mt]);
                }
                {
                    float rr = sigf(R[mt][nt][1]), zz = sigf(Z[mt][nt][1]);
                    float nn = tanhfast(I_[mt][nt][1] + rr*Hh[mt][nt][1]);
                    py[2*mt] = fmaf((1.f-zz)*nn + zz*h0.y, wc1, py[2*mt]);
                }
                {
                    float rr = sigf(R[mt][nt][2]), zz = sigf(Z[mt][nt][2]);
                    float nn = tanhfast(I_[mt][nt][2] + rr*Hh[mt][nt][2]);
                    py[2*mt+1] = fmaf((1.f-zz)*nn + zz*h1.x, wc0, py[2*mt+1]);
                }
                {
                    float rr = sigf(R[mt][nt][3]), zz = sigf(Z[mt][nt][3]);
                    float nn = tanhfast(I_[mt][nt][3] + rr*Hh[mt][nt][3]);
                    py[2*mt+1] = fmaf((1.f-zz)*nn + zz*h1.y, wc1, py[2*mt+1]);
                }
            }
        #pragma unroll
        for (int q = 0; q < 4; q++) {
            py[q] += __shfl_xor_sync(0xffffffffu, py[q], 1, 4);
            py[q] += __shfl_xor_sync(0xffffffffu, py[q], 2, 4);
        }
        if (t == 0) {
            sred[cg*128 + rb + g]      = py[0];
            sred[cg*128 + rb + 8 + g]  = py[1];
            sred[cg*128 + rb + 16 + g] = py[2];
            sred[cg*128 + rb + 24 + g] = py[3];
        }
        __syncthreads();
        if (tid < 128)
            out[row0 + tid] = sigf(sred[tid] + sred[128+tid] + sred[256+tid] + sred[384+tid] + bpv);
        __syncthreads();
    }
}

// ---------------------------------------------------------------------------
extern "C" void kernel_launch(void* const* d_in, const int* in_sizes, int n_in,
                              void* d_out, int out_size)
{
    const int*   qt  = (const int*)  d_in[1];
    const float* ht  = (const float*)d_in[2];
    const float* oh  = (const float*)d_in[3];
    const float* kc  = (const float*)d_in[4];
    const float* gr  = (const float*)d_in[5];
    const float* nw  = (const float*)d_in[6];
    const float* Ws1 = (const float*)d_in[7];
    const float* bs1 = (const float*)d_in[8];
    const float* Ws2 = (const float*)d_in[9];
    const float* bs2 = (const float*)d_in[10];
    const float* Wn1 = (const float*)d_in[11];
    const float* bn1 = (const float*)d_in[12];
    const float* Wn2 = (const float*)d_in[13];
    const float* bn2 = (const float*)d_in[14];
    const float* ea  = (const float*)d_in[15];
    const float* We  = (const float*)d_in[16];
    const float* be  = (const float*)d_in[17];
    const float* Wa  = (const float*)d_in[18];
    const float* ba  = (const float*)d_in[19];
    const float* Wih = (const float*)d_in[20];
    const float* bih = (const float*)d_in[21];
    const float* Whh = (const float*)d_in[22];
    const float* bhh = (const float*)d_in[23];
    const float* Wp  = (const float*)d_in[24];
    const float* bp  = (const float*)d_in[25];
    float* out = (float*)d_out;

    int smc = 148;
    if (cudaDeviceGetAttribute(&smc, cudaDevAttrMultiProcessorCount, 0) != cudaSuccess || smc <= 0)
        smc = 148;

    // f1: Xs4096 + H1s8192 + PW1 4096 + PW2 4096 (u32) + 384 floats = 83,456 B
    size_t smem1 = (size_t)(4096 + 8192 + 4096 + 4096) * 4 + (size_t)384 * 4;
    // f2: Xs4096 + Hs4096 + PWe2048+PWa2048+PWih6144+PWhh6144 (u32) + 960 floats = 101,504 B
    size_t smem2 = (size_t)(4096 + 4096 + 2048 + 2048 + 6144 + 6144) * 4 + (size_t)960 * 4;
    cudaFuncSetAttribute(f1_kernel, cudaFuncAttributeMaxDynamicSharedMemorySize, (int)smem1);
    cudaFuncSetAttribute(f2_kernel, cudaFuncAttributeMaxDynamicSharedMemorySize, (int)smem2);

    adj_kernel<<<1, 1024>>>(qt, oh, gr);
    maskscan_kernel<<<256, 256>>>(qt, oh);
    kcbase_kernel<<<1024, 128>>>(kc, Wn1, bn1);
    f1_kernel<<<smc*2, 512, smem1>>>(ht, nw, Wn1, Wn2, bn2);
    selfmlp_kernel<<<2048, 128>>>(ht, kc, Ws1, bs1, Ws2, bs2);
    f2_kernel<<<smc, 512, smem2>>>(ht, ea, We, be, Wa, ba, Wih, bih, Whh, bhh, Wp, bp, out);
}